// round 13
// baseline (speedup 1.0000x reference)
#include <cuda_runtime.h>
#include <cuda_fp16.h>

// TCLoss, N=2048, D=64.
// y_ijd = LOG2E * log N(z_i,d ; m_j,d, exp(lv_j,d)) = a_jd*z^2 + b_jd*z + g_jd
// out = mean_i [ LN2*( sum_d log2 sum_j 2^y  -  log2sumexp2_j sum_d y ) ]
//
// k0: precompute coeffs (AB float4 (a0,a1,b0,b1), G float2 per (j,dim-pair)).
// k1: persistent main. 128-thread blocks, 5 resident/SM (640 thr -> 102-reg
//     cap, 5 warps/SMSP for latency hiding). Warp owns 2 i's, lane owns dims
//     {2l,2l+1}; 32-j smem tile (24 KB). y in fp32 FMA; per-dim exps via
//     ex2.approx.f16x2, half2 pair accumulation, fp32 flush per 8-j batch.
//     Scalar S: rotated SEL-free multi-value butterfly (9 SHFL + 9 FADD per
//     8 classes), software-pipelined; per-lane fp32 online LSE, class-merged
//     once per unit.
// k2: per-i reduction over 64 chunk partials. k3: mean.

#define LOG2E   1.44269504088896340736f
#define LN2     0.69314718055994530942f
#define LOG2PI  1.83787706640934548356f
#define NEG_INF __int_as_float(0xff800000)

#define NPTS    2048
#define DDIM    64
#define TJ      32                   // j's per chunk
#define NCHUNK  (NPTS / TJ)          // 64
#define TPB     128                  // threads per block (4 warps)
#define IPB     8                    // i's per block (4 warps x 2)
#define NGROUP  (NPTS / IPB)         // 256
#define NUNITS  (NGROUP * NCHUNK)    // 16384
#define NBLOCKS 740                  // 148 SMs x 5 resident blocks

// Static scratch (no allocation).
__device__ float4 g_cAB[NPTS * DDIM / 2];       // (a0,a1,b0,b1) per (j, dim-pair)
__device__ float2 g_cG[NPTS * DDIM / 2];        // (g0,g1) per (j, dim-pair)
__device__ float g_psum[NPTS * NCHUNK * DDIM];  // per-(i,chunk) per-dim sums of 2^y
__device__ float g_pm[NPTS * NCHUNK];           // per-(i,chunk) LSE max (log2)
__device__ float g_ps[NPTS * NCHUNK];           // per-(i,chunk) LSE scaled sum
__device__ float g_val[NPTS];                   // per-i result

static __device__ __forceinline__ float ex2f(float x) {
    float r; asm("ex2.approx.ftz.f32 %0, %1;" : "=f"(r) : "f"(x)); return r;
}
static __device__ __forceinline__ float lg2f(float x) {
    float r; asm("lg2.approx.f32 %0, %1;" : "=f"(r) : "f"(x)); return r;
}
// Pack two fp32 -> half2 (single F2FP.PACK), then 2^x on both halves (1 MUFU).
static __device__ __forceinline__ __half2 ex2h2(float x, float y) {
    __half2 h = __floats2half2_rn(x, y);
    __half2 r;
    asm("ex2.approx.f16x2 %0, %1;"
        : "=r"(*reinterpret_cast<unsigned*>(&r))
        : "r"(*reinterpret_cast<const unsigned*>(&h)));
    return r;
}

// Online base-2 logsumexp update with a single EX2.
static __device__ __forceinline__ void lse_up(float& m, float& s, float S) {
    const float d = S - m;
    const float e = ex2f(-fabsf(d));   // ex2(-inf)=0 handles first call (m=-inf)
    if (d > 0.f) { s = fmaf(s, e, 1.f); m = S; }
    else         { s += e; }
}

// Rotated multi-value warp reduction (SEL-free): lane l's t[k] holds the
// partial for j-class (k ^ sigma), sigma = (l>>2)&7. Returns, on every lane,
// the full 32-lane sum of class (lane>>2)&7.
static __device__ __forceinline__ float mred8rot(float t[8]) {
    #pragma unroll
    for (int k = 0; k < 4; ++k)
        t[k] += __shfl_xor_sync(0xffffffffu, t[k ^ 4], 16);
    #pragma unroll
    for (int k = 0; k < 2; ++k)
        t[k] += __shfl_xor_sync(0xffffffffu, t[k ^ 2], 8);
    t[0] += __shfl_xor_sync(0xffffffffu, t[1], 4);
    float v = t[0];
    v += __shfl_xor_sync(0xffffffffu, v, 2);
    v += __shfl_xor_sync(0xffffffffu, v, 1);
    return v;
}

// Merge per-lane (m,s) across the 8 j-classes (lane bits 2..4).
static __device__ __forceinline__ void merge_classes(float& m, float& s) {
    #pragma unroll
    for (int off = 4; off <= 16; off <<= 1) {
        const float mo = __shfl_xor_sync(0xffffffffu, m, off);
        const float so = __shfl_xor_sync(0xffffffffu, s, off);
        const float M  = fmaxf(m, mo);
        s = s * ex2f(m - M) + so * ex2f(mo - M);
        m = M;
    }
}

static __device__ __forceinline__ void coeffs(float mm, float lv,
                                              float& a, float& b, float& g) {
    const float iv = ex2f(-LOG2E * lv);          // exp(-lv)
    const float w  = -0.5f * LOG2E * iv;
    const float t  = w * mm;
    a = w;
    b = -(t + t);
    g = fmaf(t, mm, -0.5f * LOG2E * (lv + LOG2PI));
}

// k0: precompute packed coefficient arrays.
__global__ __launch_bounds__(256)
void tc_coeff_kernel(const float* __restrict__ zmean, const float* __restrict__ zlv)
{
    const int e = blockIdx.x * 256 + threadIdx.x;   // [0, 32768)
    const int j = e >> 4;
    const int f = e & 15;                           // float4 index within row
    const float4 mv = ((const float4*)zmean)[e];
    const float4 lv = ((const float4*)zlv)[e];
    float a0, b0, g0, a1, b1, g1, a2, b2, g2, a3, b3, g3;
    coeffs(mv.x, lv.x, a0, b0, g0);
    coeffs(mv.y, lv.y, a1, b1, g1);
    coeffs(mv.z, lv.z, a2, b2, g2);
    coeffs(mv.w, lv.w, a3, b3, g3);
    g_cAB[(j << 5) + 2 * f]     = make_float4(a0, a1, b0, b1);
    g_cAB[(j << 5) + 2 * f + 1] = make_float4(a2, a3, b2, b3);
    g_cG[(j << 5) + 2 * f]      = make_float2(g0, g1);
    g_cG[(j << 5) + 2 * f + 1]  = make_float2(g2, g3);
}

// k1: main pairwise kernel.
__global__ __launch_bounds__(TPB, 5)
void tc_main_kernel(const float* __restrict__ z)
{
    __shared__ float4 shAB[TJ * 32];   // 16 KB
    __shared__ float2 shG[TJ * 32];    // 8 KB

    const int tid  = threadIdx.x;
    const int wid  = tid >> 5;
    const unsigned lane = tid & 31;
    const unsigned sig  = (lane >> 2) & 7;   // rotation for SEL-free butterfly

    for (int u = blockIdx.x; u < NUNITS; u += NBLOCKS) {
        const int ig = u & (NGROUP - 1);
        const int c  = u >> 8;
        const int js = c * TJ;

        __syncthreads();  // previous unit's readers done
        {
            const float4* pab = g_cAB + js * 32;
            const float4* pg  = (const float4*)(g_cG + js * 32);
            #pragma unroll
            for (int e = tid; e < TJ * 32; e += TPB)
                shAB[e] = pab[e];
            #pragma unroll
            for (int e = tid; e < TJ * 16; e += TPB)
                ((float4*)shG)[e] = pg[e];
        }
        __syncthreads();

        const int i0 = ig * IPB + wid * 2;
        const float2 zva = ((const float2*)z)[i0 * 32 + lane];
        const float2 zvb = ((const float2*)z)[(i0 + 1) * 32 + lane];
        const float zA0 = zva.x, zA1 = zva.y, zB0 = zvb.x, zB1 = zvb.y;
        const float qA0 = zA0 * zA0, qA1 = zA1 * zA1;
        const float qB0 = zB0 * zB0, qB1 = zB1 * zB1;

        float aA0 = 0.f, aA1 = 0.f, aB0 = 0.f, aB1 = 0.f;
        float mA = NEG_INF, sA = 0.f, mB = NEG_INF, sB = 0.f;

        float tPA[8], tPB[8];   // previous batch's scalar partials (rotated)

        // Software pipeline: compute batch jb, then reduce batch jb-1.
        #pragma unroll
        for (int jb = 0; jb < TJ / 8; ++jb) {
            float tCA[8], tCB[8];
            __half2 eqA[4], eqB[4];    // pairwise half2 exp accumulators
            #pragma unroll
            for (int k = 0; k < 8; ++k) {
                // rotated class assignment: this lane's register k covers
                // j-class k^sig of the batch.
                const int j = jb * 8 + (k ^ (int)sig);
                const float4 ab = shAB[j * 32 + lane];
                const float2 g  = shG[j * 32 + lane];
                const float yA0 = fmaf(ab.x, qA0, fmaf(ab.z, zA0, g.x));
                const float yA1 = fmaf(ab.y, qA1, fmaf(ab.w, zA1, g.y));
                const float yB0 = fmaf(ab.x, qB0, fmaf(ab.z, zB0, g.x));
                const float yB1 = fmaf(ab.y, qB1, fmaf(ab.w, zB1, g.y));
                const __half2 eA = ex2h2(yA0, yA1);
                const __half2 eB = ex2h2(yB0, yB1);
                if (k & 1) {
                    eqA[k >> 1] = __hadd2(eqA[k >> 1], eA);
                    eqB[k >> 1] = __hadd2(eqB[k >> 1], eB);
                } else {
                    eqA[k >> 1] = eA;
                    eqB[k >> 1] = eB;
                }
                tCA[k] = yA0 + yA1;
                tCB[k] = yB0 + yB1;
            }
            // tree-flush half2 exp partials to fp32 accumulators
            {
                const __half2 rA = __hadd2(__hadd2(eqA[0], eqA[1]),
                                           __hadd2(eqA[2], eqA[3]));
                const __half2 rB = __hadd2(__hadd2(eqB[0], eqB[1]),
                                           __hadd2(eqB[2], eqB[3]));
                const float2 fA = __half22float2(rA);
                const float2 fB = __half22float2(rB);
                aA0 += fA.x; aA1 += fA.y;
                aB0 += fB.x; aB1 += fB.y;
            }
            if (jb > 0) {
                lse_up(mA, sA, mred8rot(tPA));
                lse_up(mB, sB, mred8rot(tPB));
            }
            #pragma unroll
            for (int k = 0; k < 8; ++k) { tPA[k] = tCA[k]; tPB[k] = tCB[k]; }
        }
        lse_up(mA, sA, mred8rot(tPA));
        lse_up(mB, sB, mred8rot(tPB));

        ((float2*)g_psum)[(i0 * NCHUNK + c) * 32 + lane]       = make_float2(aA0, aA1);
        ((float2*)g_psum)[((i0 + 1) * NCHUNK + c) * 32 + lane] = make_float2(aB0, aB1);
        merge_classes(mA, sA);
        merge_classes(mB, sB);
        if (lane == 0) {
            g_pm[i0 * NCHUNK + c] = mA;
            g_ps[i0 * NCHUNK + c] = sA;
            g_pm[(i0 + 1) * NCHUNK + c] = mB;
            g_ps[(i0 + 1) * NCHUNK + c] = sB;
        }
    }
}

// k2: one warp per i combines the 64 chunk partials.
__global__ __launch_bounds__(256)
void tc_reduce_i()
{
    const int wid  = threadIdx.x >> 5;
    const int lane = threadIdx.x & 31;
    const int i    = blockIdx.x * 8 + wid;

    float s0 = 0.f, s1 = 0.f;
    const float2* P = (const float2*)g_psum;
    #pragma unroll
    for (int cc = 0; cc < NCHUNK; ++cc) {
        const float2 v = P[(i * NCHUNK + cc) * 32 + lane];
        s0 += v.x; s1 += v.y;
    }
    float t = lg2f(s0) + lg2f(s1);
    #pragma unroll
    for (int off = 16; off; off >>= 1)
        t += __shfl_xor_sync(0xffffffffu, t, off);

    // merge 64 chunk (m,s): two per lane, then butterfly
    float ml = g_pm[i * NCHUNK + lane];
    float sl = g_ps[i * NCHUNK + lane];
    {
        const float mc = g_pm[i * NCHUNK + 32 + lane];
        const float sc = g_ps[i * NCHUNK + 32 + lane];
        const float M  = fmaxf(ml, mc);
        sl = sl * ex2f(ml - M) + sc * ex2f(mc - M);
        ml = M;
    }
    #pragma unroll
    for (int off = 16; off; off >>= 1) {
        const float mo = __shfl_xor_sync(0xffffffffu, ml, off);
        const float so = __shfl_xor_sync(0xffffffffu, sl, off);
        const float M  = fmaxf(ml, mo);
        sl = sl * ex2f(ml - M) + so * ex2f(mo - M);
        ml = M;
    }

    if (lane == 0)
        g_val[i] = LN2 * (t - (ml + lg2f(sl)));
}

// k3: deterministic final mean (256 threads, shuffle-based).
__global__ __launch_bounds__(256)
void tc_final(float* __restrict__ out)
{
    __shared__ float sm[8];
    const int t = threadIdx.x;
    float v = 0.f;
    #pragma unroll
    for (int k = 0; k < 8; ++k)
        v += g_val[t + k * 256];
    #pragma unroll
    for (int off = 16; off; off >>= 1)
        v += __shfl_xor_sync(0xffffffffu, v, off);
    if ((t & 31) == 0) sm[t >> 5] = v;
    __syncthreads();
    if (t == 0) {
        float r = 0.f;
        #pragma unroll
        for (int k = 0; k < 8; ++k) r += sm[k];
        out[0] = r * (1.0f / (float)NPTS);
    }
}

extern "C" void kernel_launch(void* const* d_in, const int* in_sizes, int n_in,
                              void* d_out, int out_size)
{
    const float* z  = (const float*)d_in[0];
    const float* zm = (const float*)d_in[1];
    const float* zl = (const float*)d_in[2];
    tc_coeff_kernel<<<NPTS * DDIM / 1024, 256>>>(zm, zl);
    tc_main_kernel<<<NBLOCKS, TPB>>>(z);
    tc_reduce_i<<<NPTS / 8, 256>>>();
    tc_final<<<1, 256>>>((float*)d_out);
}

// round 15
// speedup vs baseline: 1.1347x; 1.1347x over previous
#include <cuda_runtime.h>
#include <cuda_fp16.h>

// TCLoss, N=2048, D=64.
// y_ijd = LOG2E * log N(z_i,d ; m_j,d, exp(lv_j,d)) = a_jd*z^2 + b_jd*z + g_jd
// out = mean_i [ LN2*( sum_d log2 sum_j 2^y  -  log2sumexp2_j sum_d y ) ]
//
// k0: precompute coeffs (AB float4 (a0,a1,b0,b1), G float2 per (j,dim-pair)).
// k1: persistent main (R11 hot loop, 2 blocks/SM). DOUBLE-BUFFERED j-tiles:
//     two 48 KB smem buffers, next unit's tile fetched with cp.async.cg while
//     the current unit computes -> L2 latency off the critical path. Warp
//     owns 2 i's, lane owns dims {2l,2l+1}. fp32 FMA; f16x2 per-dim exps;
//     rotated SEL-free butterfly + fp32 online LSE, software-pipelined.
//     (R15 fix: G read pointer stride 2048 float2 = 16 KB, matching prefetch.)
// k2: per-i reduction over 32 chunk partials. k3: mean.

#define LOG2E   1.44269504088896340736f
#define LN2     0.69314718055994530942f
#define LOG2PI  1.83787706640934548356f
#define NEG_INF __int_as_float(0xff800000)

#define NPTS    2048
#define DDIM    64
#define TJ      64                   // j's per chunk
#define NCHUNK  (NPTS / TJ)          // 32
#define IPB     16                   // i's per block (8 warps x 2)
#define NGROUP  (NPTS / IPB)         // 128
#define NUNITS  (NGROUP * NCHUNK)    // 4096
#define NBLOCKS 296                  // 148 SMs x 2 resident blocks
#define SMEM_BYTES (2 * (48 * 1024)) // two 48 KB tile buffers

// Static scratch (no allocation).
__device__ float4 g_cAB[NPTS * DDIM / 2];       // (a0,a1,b0,b1) per (j, dim-pair)
__device__ float2 g_cG[NPTS * DDIM / 2];        // (g0,g1) per (j, dim-pair)
__device__ float g_psum[NPTS * NCHUNK * DDIM];  // per-(i,chunk) per-dim sums of 2^y
__device__ float g_pm[NPTS * NCHUNK];           // per-(i,chunk) LSE max (log2)
__device__ float g_ps[NPTS * NCHUNK];           // per-(i,chunk) LSE scaled sum
__device__ float g_val[NPTS];                   // per-i result

static __device__ __forceinline__ float ex2f(float x) {
    float r; asm("ex2.approx.ftz.f32 %0, %1;" : "=f"(r) : "f"(x)); return r;
}
static __device__ __forceinline__ float lg2f(float x) {
    float r; asm("lg2.approx.f32 %0, %1;" : "=f"(r) : "f"(x)); return r;
}
// Pack two fp32 -> half2 (single F2FP.PACK), then 2^x on both halves (1 MUFU).
static __device__ __forceinline__ __half2 ex2h2(float x, float y) {
    __half2 h = __floats2half2_rn(x, y);
    __half2 r;
    asm("ex2.approx.f16x2 %0, %1;"
        : "=r"(*reinterpret_cast<unsigned*>(&r))
        : "r"(*reinterpret_cast<const unsigned*>(&h)));
    return r;
}
// 16-byte async copy, L1-bypass (L2 -> smem).
static __device__ __forceinline__ void cpa16(unsigned dst, const void* src) {
    asm volatile("cp.async.cg.shared.global [%0], [%1], 16;"
                 :: "r"(dst), "l"(src));
}

// Online base-2 logsumexp update with a single EX2.
static __device__ __forceinline__ void lse_up(float& m, float& s, float S) {
    const float d = S - m;
    const float e = ex2f(-fabsf(d));   // ex2(-inf)=0 handles first call (m=-inf)
    if (d > 0.f) { s = fmaf(s, e, 1.f); m = S; }
    else         { s += e; }
}

// Rotated multi-value warp reduction (SEL-free): lane l's t[k] holds the
// partial for j-class (k ^ sigma), sigma = (l>>2)&7. Returns, on every lane,
// the full 32-lane sum of class (lane>>2)&7.
static __device__ __forceinline__ float mred8rot(float t[8]) {
    #pragma unroll
    for (int k = 0; k < 4; ++k)
        t[k] += __shfl_xor_sync(0xffffffffu, t[k ^ 4], 16);
    #pragma unroll
    for (int k = 0; k < 2; ++k)
        t[k] += __shfl_xor_sync(0xffffffffu, t[k ^ 2], 8);
    t[0] += __shfl_xor_sync(0xffffffffu, t[1], 4);
    float v = t[0];
    v += __shfl_xor_sync(0xffffffffu, v, 2);
    v += __shfl_xor_sync(0xffffffffu, v, 1);
    return v;
}

// Merge per-lane (m,s) across the 8 j-classes (lane bits 2..4).
static __device__ __forceinline__ void merge_classes(float& m, float& s) {
    #pragma unroll
    for (int off = 4; off <= 16; off <<= 1) {
        const float mo = __shfl_xor_sync(0xffffffffu, m, off);
        const float so = __shfl_xor_sync(0xffffffffu, s, off);
        const float M  = fmaxf(m, mo);
        s = s * ex2f(m - M) + so * ex2f(mo - M);
        m = M;
    }
}

static __device__ __forceinline__ void coeffs(float mm, float lv,
                                              float& a, float& b, float& g) {
    const float iv = ex2f(-LOG2E * lv);          // exp(-lv)
    const float w  = -0.5f * LOG2E * iv;
    const float t  = w * mm;
    a = w;
    b = -(t + t);
    g = fmaf(t, mm, -0.5f * LOG2E * (lv + LOG2PI));
}

// k0: precompute packed coefficient arrays.
__global__ __launch_bounds__(256)
void tc_coeff_kernel(const float* __restrict__ zmean, const float* __restrict__ zlv)
{
    const int e = blockIdx.x * 256 + threadIdx.x;   // [0, 32768)
    const int j = e >> 4;
    const int f = e & 15;                           // float4 index within row
    const float4 mv = ((const float4*)zmean)[e];
    const float4 lv = ((const float4*)zlv)[e];
    float a0, b0, g0, a1, b1, g1, a2, b2, g2, a3, b3, g3;
    coeffs(mv.x, lv.x, a0, b0, g0);
    coeffs(mv.y, lv.y, a1, b1, g1);
    coeffs(mv.z, lv.z, a2, b2, g2);
    coeffs(mv.w, lv.w, a3, b3, g3);
    g_cAB[(j << 5) + 2 * f]     = make_float4(a0, a1, b0, b1);
    g_cAB[(j << 5) + 2 * f + 1] = make_float4(a2, a3, b2, b3);
    g_cG[(j << 5) + 2 * f]      = make_float2(g0, g1);
    g_cG[(j << 5) + 2 * f + 1]  = make_float2(g2, g3);
}

// k1: main pairwise kernel (double-buffered tiles).
__global__ __launch_bounds__(256, 2)
void tc_main_kernel(const float* __restrict__ z)
{
    extern __shared__ char smem[];
    // layout: AB0[2048]f4 | AB1[2048]f4 | G0[2048]f2 | G1[2048]f2
    float4* shAB = (float4*)smem;                       // 2 x 32 KB
    float2* shG  = (float2*)(smem + 2 * 32 * 1024);     // 2 x 16 KB
    unsigned sbase;
    asm("{ .reg .u64 t; cvta.to.shared.u64 t, %1; cvt.u32.u64 %0, t; }"
        : "=r"(sbase) : "l"(smem));

    const int tid  = threadIdx.x;
    const int wid  = tid >> 5;
    const unsigned lane = tid & 31;
    const unsigned sig  = (lane >> 2) & 7;   // rotation for SEL-free butterfly

    // issue the async tile fetch for unit u into buffer b (12 x 16B / thread)
    auto prefetch = [&](int u, int b) {
        const int js = (u >> 7) * TJ;
        const float4* pab = g_cAB + js * 32;
        const float4* pg4 = (const float4*)(g_cG + js * 32);
        const unsigned dab = sbase + b * 32768;
        const unsigned dg  = sbase + 65536 + b * 16384;
        #pragma unroll
        for (int e = tid; e < 2048; e += 256)
            cpa16(dab + e * 16, pab + e);
        #pragma unroll
        for (int e = tid; e < 1024; e += 256)
            cpa16(dg + e * 16, pg4 + e);
    };

    int u = blockIdx.x;
    prefetch(u, 0);
    asm volatile("cp.async.commit_group;");

    for (int idx = 0; u < NUNITS; u += NBLOCKS, ++idx) {
        const int p = idx & 1;
        __syncthreads();   // all warps done reading buf[1-p] (prev unit)
        const int un = u + NBLOCKS;
        if (un < NUNITS) prefetch(un, 1 - p);
        asm volatile("cp.async.commit_group;");
        asm volatile("cp.async.wait_group 1;");   // buf[p] data arrived
        __syncthreads();   // all threads' copies visible

        const float4* AB = shAB + p * 2048;
        const float2* G  = shG  + p * 2048;   // 16 KB stride (R15 fix)
        const int ig = u & (NGROUP - 1);
        const int c  = u >> 7;

        const int i0 = ig * IPB + wid * 2;
        const float2 zva = ((const float2*)z)[i0 * 32 + lane];
        const float2 zvb = ((const float2*)z)[(i0 + 1) * 32 + lane];
        const float zA0 = zva.x, zA1 = zva.y, zB0 = zvb.x, zB1 = zvb.y;
        const float qA0 = zA0 * zA0, qA1 = zA1 * zA1;
        const float qB0 = zB0 * zB0, qB1 = zB1 * zB1;

        float aA0 = 0.f, aA1 = 0.f, aB0 = 0.f, aB1 = 0.f;
        float mA = NEG_INF, sA = 0.f, mB = NEG_INF, sB = 0.f;

        float tPA[8], tPB[8];   // previous batch's scalar partials (rotated)

        // Software pipeline: compute batch jb, then reduce batch jb-1.
        #pragma unroll
        for (int jb = 0; jb < TJ / 8; ++jb) {
            float tCA[8], tCB[8];
            __half2 eqA[4], eqB[4];    // pairwise half2 exp accumulators
            #pragma unroll
            for (int k = 0; k < 8; ++k) {
                // rotated class assignment: this lane's register k covers
                // j-class k^sig of the batch.
                const int j = jb * 8 + (k ^ (int)sig);
                const float4 ab = AB[j * 32 + lane];
                const float2 g  = G[j * 32 + lane];
                const float yA0 = fmaf(ab.x, qA0, fmaf(ab.z, zA0, g.x));
                const float yA1 = fmaf(ab.y, qA1, fmaf(ab.w, zA1, g.y));
                const float yB0 = fmaf(ab.x, qB0, fmaf(ab.z, zB0, g.x));
                const float yB1 = fmaf(ab.y, qB1, fmaf(ab.w, zB1, g.y));
                const __half2 eA = ex2h2(yA0, yA1);
                const __half2 eB = ex2h2(yB0, yB1);
                if (k & 1) {
                    eqA[k >> 1] = __hadd2(eqA[k >> 1], eA);
                    eqB[k >> 1] = __hadd2(eqB[k >> 1], eB);
                } else {
                    eqA[k >> 1] = eA;
                    eqB[k >> 1] = eB;
                }
                tCA[k] = yA0 + yA1;
                tCB[k] = yB0 + yB1;
            }
            // tree-flush half2 exp partials to fp32 accumulators
            {
                const __half2 rA = __hadd2(__hadd2(eqA[0], eqA[1]),
                                           __hadd2(eqA[2], eqA[3]));
                const __half2 rB = __hadd2(__hadd2(eqB[0], eqB[1]),
                                           __hadd2(eqB[2], eqB[3]));
                const float2 fA = __half22float2(rA);
                const float2 fB = __half22float2(rB);
                aA0 += fA.x; aA1 += fA.y;
                aB0 += fB.x; aB1 += fB.y;
            }
            if (jb > 0) {
                lse_up(mA, sA, mred8rot(tPA));
                lse_up(mB, sB, mred8rot(tPB));
            }
            #pragma unroll
            for (int k = 0; k < 8; ++k) { tPA[k] = tCA[k]; tPB[k] = tCB[k]; }
        }
        lse_up(mA, sA, mred8rot(tPA));
        lse_up(mB, sB, mred8rot(tPB));

        ((float2*)g_psum)[(i0 * NCHUNK + c) * 32 + lane]       = make_float2(aA0, aA1);
        ((float2*)g_psum)[((i0 + 1) * NCHUNK + c) * 32 + lane] = make_float2(aB0, aB1);
        merge_classes(mA, sA);
        merge_classes(mB, sB);
        if (lane == 0) {
            g_pm[i0 * NCHUNK + c] = mA;
            g_ps[i0 * NCHUNK + c] = sA;
            g_pm[(i0 + 1) * NCHUNK + c] = mB;
            g_ps[(i0 + 1) * NCHUNK + c] = sB;
        }
    }
}

// k2: one warp per i combines the 32 chunk partials.
__global__ __launch_bounds__(256)
void tc_reduce_i()
{
    const int wid  = threadIdx.x >> 5;
    const int lane = threadIdx.x & 31;
    const int i    = blockIdx.x * 8 + wid;

    float s0 = 0.f, s1 = 0.f;
    const float2* P = (const float2*)g_psum;
    #pragma unroll
    for (int cc = 0; cc < NCHUNK; ++cc) {
        const float2 v = P[(i * NCHUNK + cc) * 32 + lane];
        s0 += v.x; s1 += v.y;
    }
    float t = lg2f(s0) + lg2f(s1);
    #pragma unroll
    for (int off = 16; off; off >>= 1)
        t += __shfl_xor_sync(0xffffffffu, t, off);

    float ml = g_pm[i * NCHUNK + lane];   // NCHUNK==32: one chunk per lane
    float sl = g_ps[i * NCHUNK + lane];
    #pragma unroll
    for (int off = 16; off; off >>= 1) {
        const float mo = __shfl_xor_sync(0xffffffffu, ml, off);
        const float so = __shfl_xor_sync(0xffffffffu, sl, off);
        const float M  = fmaxf(ml, mo);
        sl = sl * ex2f(ml - M) + so * ex2f(mo - M);
        ml = M;
    }

    if (lane == 0)
        g_val[i] = LN2 * (t - (ml + lg2f(sl)));
}

// k3: deterministic final mean (256 threads, shuffle-based).
__global__ __launch_bounds__(256)
void tc_final(float* __restrict__ out)
{
    __shared__ float sm[8];
    const int t = threadIdx.x;
    float v = 0.f;
    #pragma unroll
    for (int k = 0; k < 8; ++k)
        v += g_val[t + k * 256];
    #pragma unroll
    for (int off = 16; off; off >>= 1)
        v += __shfl_xor_sync(0xffffffffu, v, off);
    if ((t & 31) == 0) sm[t >> 5] = v;
    __syncthreads();
    if (t == 0) {
        float r = 0.f;
        #pragma unroll
        for (int k = 0; k < 8; ++k) r += sm[k];
        out[0] = r * (1.0f / (float)NPTS);
    }
}

extern "C" void kernel_launch(void* const* d_in, const int* in_sizes, int n_in,
                              void* d_out, int out_size)
{
    const float* z  = (const float*)d_in[0];
    const float* zm = (const float*)d_in[1];
    const float* zl = (const float*)d_in[2];
    cudaFuncSetAttribute(tc_main_kernel,
                         cudaFuncAttributeMaxDynamicSharedMemorySize, SMEM_BYTES);
    tc_coeff_kernel<<<NPTS * DDIM / 1024, 256>>>(zm, zl);
    tc_main_kernel<<<NBLOCKS, 256, SMEM_BYTES>>>(z);
    tc_reduce_i<<<NPTS / 8, 256>>>();
    tc_final<<<1, 256>>>((float*)d_out);
}

// round 16
// speedup vs baseline: 1.1678x; 1.0291x over previous
#include <cuda_runtime.h>
#include <cuda_fp16.h>

// TCLoss, N=2048, D=64.
// y_ijd = LOG2E * log N(z_i,d ; m_j,d, exp(lv_j,d)) = a_jd*z^2 + b_jd*z + g_jd
// out = mean_i [ LN2*( sum_d log2 sum_j 2^y  -  log2sumexp2_j sum_d y ) ]
//
// k0: precompute coeffs (AB float4 (a0,a1,b0,b1), G float2 per (j,dim-pair)).
// k1: persistent main — BIT-IDENTICAL hot loop to the R11 winner (2 blocks/SM,
//     software pipeline, rotated SEL-free butterfly, f16x2 per-dim exps).
//     Only the psum store changed: half2 scaled by 64 (4B/lane, halves k2's
//     read traffic; fp32 accumulators unchanged).
// k2: per-i reduction over 32 chunk partials + FUSED final mean via the
//     last-block pattern (threadfence + atomic counter, self-resetting for
//     graph replay, fixed-tree sum -> deterministic).

#define LOG2E   1.44269504088896340736f
#define LN2     0.69314718055994530942f
#define LOG2PI  1.83787706640934548356f
#define NEG_INF __int_as_float(0xff800000)

#define NPTS    2048
#define DDIM    64
#define TJ      64                   // j's per chunk
#define NCHUNK  (NPTS / TJ)          // 32
#define IPB     16                   // i's per block (8 warps x 2)
#define NGROUP  (NPTS / IPB)         // 128
#define NUNITS  (NGROUP * NCHUNK)    // 4096
#define NBLOCKS 296                  // 148 SMs x 2 resident blocks
#define K2GRID  (NPTS / 8)           // 256 blocks in the reduce kernel

// Static scratch (no allocation).
__device__ float4  g_cAB[NPTS * DDIM / 2];        // (a0,a1,b0,b1) per (j, dim-pair)
__device__ float2  g_cG[NPTS * DDIM / 2];         // (g0,g1) per (j, dim-pair)
__device__ __half2 g_psumh[NPTS * NCHUNK * 32];   // per-(i,chunk) per-dim-pair sums (x64)
__device__ float   g_pm[NPTS * NCHUNK];           // per-(i,chunk) LSE max (log2)
__device__ float   g_ps[NPTS * NCHUNK];           // per-(i,chunk) LSE scaled sum
__device__ float   g_val[NPTS];                   // per-i result
__device__ int     g_count;                       // last-block counter (zero-init)

static __device__ __forceinline__ float ex2f(float x) {
    float r; asm("ex2.approx.ftz.f32 %0, %1;" : "=f"(r) : "f"(x)); return r;
}
static __device__ __forceinline__ float lg2f(float x) {
    float r; asm("lg2.approx.f32 %0, %1;" : "=f"(r) : "f"(x)); return r;
}
// Pack two fp32 -> half2 (single F2FP.PACK), then 2^x on both halves (1 MUFU).
static __device__ __forceinline__ __half2 ex2h2(float x, float y) {
    __half2 h = __floats2half2_rn(x, y);
    __half2 r;
    asm("ex2.approx.f16x2 %0, %1;"
        : "=r"(*reinterpret_cast<unsigned*>(&r))
        : "r"(*reinterpret_cast<const unsigned*>(&h)));
    return r;
}

// Online base-2 logsumexp update with a single EX2.
static __device__ __forceinline__ void lse_up(float& m, float& s, float S) {
    const float d = S - m;
    const float e = ex2f(-fabsf(d));   // ex2(-inf)=0 handles first call (m=-inf)
    if (d > 0.f) { s = fmaf(s, e, 1.f); m = S; }
    else         { s += e; }
}

// Rotated multi-value warp reduction (SEL-free): lane l's t[k] holds the
// partial for j-class (k ^ sigma), sigma = (l>>2)&7. Returns, on every lane,
// the full 32-lane sum of class (lane>>2)&7.
static __device__ __forceinline__ float mred8rot(float t[8]) {
    #pragma unroll
    for (int k = 0; k < 4; ++k)
        t[k] += __shfl_xor_sync(0xffffffffu, t[k ^ 4], 16);
    #pragma unroll
    for (int k = 0; k < 2; ++k)
        t[k] += __shfl_xor_sync(0xffffffffu, t[k ^ 2], 8);
    t[0] += __shfl_xor_sync(0xffffffffu, t[1], 4);
    float v = t[0];
    v += __shfl_xor_sync(0xffffffffu, v, 2);
    v += __shfl_xor_sync(0xffffffffu, v, 1);
    return v;
}

// Merge per-lane (m,s) across the 8 j-classes (lane bits 2..4).
static __device__ __forceinline__ void merge_classes(float& m, float& s) {
    #pragma unroll
    for (int off = 4; off <= 16; off <<= 1) {
        const float mo = __shfl_xor_sync(0xffffffffu, m, off);
        const float so = __shfl_xor_sync(0xffffffffu, s, off);
        const float M  = fmaxf(m, mo);
        s = s * ex2f(m - M) + so * ex2f(mo - M);
        m = M;
    }
}

static __device__ __forceinline__ void coeffs(float mm, float lv,
                                              float& a, float& b, float& g) {
    const float iv = ex2f(-LOG2E * lv);          // exp(-lv)
    const float w  = -0.5f * LOG2E * iv;
    const float t  = w * mm;
    a = w;
    b = -(t + t);
    g = fmaf(t, mm, -0.5f * LOG2E * (lv + LOG2PI));
}

// k0: precompute packed coefficient arrays.
__global__ __launch_bounds__(256)
void tc_coeff_kernel(const float* __restrict__ zmean, const float* __restrict__ zlv)
{
    const int e = blockIdx.x * 256 + threadIdx.x;   // [0, 32768)
    const int j = e >> 4;
    const int f = e & 15;                           // float4 index within row
    const float4 mv = ((const float4*)zmean)[e];
    const float4 lv = ((const float4*)zlv)[e];
    float a0, b0, g0, a1, b1, g1, a2, b2, g2, a3, b3, g3;
    coeffs(mv.x, lv.x, a0, b0, g0);
    coeffs(mv.y, lv.y, a1, b1, g1);
    coeffs(mv.z, lv.z, a2, b2, g2);
    coeffs(mv.w, lv.w, a3, b3, g3);
    g_cAB[(j << 5) + 2 * f]     = make_float4(a0, a1, b0, b1);
    g_cAB[(j << 5) + 2 * f + 1] = make_float4(a2, a3, b2, b3);
    g_cG[(j << 5) + 2 * f]      = make_float2(g0, g1);
    g_cG[(j << 5) + 2 * f + 1]  = make_float2(g2, g3);
}

// k1: main pairwise kernel (R11 hot loop; psum stored as half2 x64).
__global__ __launch_bounds__(256, 2)
void tc_main_kernel(const float* __restrict__ z)
{
    __shared__ float4 shAB[TJ * 32];   // 32 KB
    __shared__ float2 shG[TJ * 32];    // 16 KB

    const int tid  = threadIdx.x;
    const int wid  = tid >> 5;
    const unsigned lane = tid & 31;
    const unsigned sig  = (lane >> 2) & 7;   // rotation for SEL-free butterfly

    for (int u = blockIdx.x; u < NUNITS; u += NBLOCKS) {
        const int ig = u & (NGROUP - 1);
        const int c  = u >> 7;
        const int js = c * TJ;

        __syncthreads();  // previous unit's readers done
        {
            const float4* pab = g_cAB + js * 32;
            const float4* pg  = (const float4*)(g_cG + js * 32);
            #pragma unroll
            for (int e = tid; e < TJ * 32; e += 256)
                shAB[e] = pab[e];
            #pragma unroll
            for (int e = tid; e < TJ * 16; e += 256)
                ((float4*)shG)[e] = pg[e];
        }
        __syncthreads();

        const int i0 = ig * IPB + wid * 2;
        const float2 zva = ((const float2*)z)[i0 * 32 + lane];
        const float2 zvb = ((const float2*)z)[(i0 + 1) * 32 + lane];
        const float zA0 = zva.x, zA1 = zva.y, zB0 = zvb.x, zB1 = zvb.y;
        const float qA0 = zA0 * zA0, qA1 = zA1 * zA1;
        const float qB0 = zB0 * zB0, qB1 = zB1 * zB1;

        float aA0 = 0.f, aA1 = 0.f, aB0 = 0.f, aB1 = 0.f;
        float mA = NEG_INF, sA = 0.f, mB = NEG_INF, sB = 0.f;

        float tPA[8], tPB[8];   // previous batch's scalar partials (rotated)

        // Software pipeline: compute batch jb, then reduce batch jb-1.
        #pragma unroll
        for (int jb = 0; jb < TJ / 8; ++jb) {
            float tCA[8], tCB[8];
            __half2 eqA[4], eqB[4];    // pairwise half2 exp accumulators
            #pragma unroll
            for (int k = 0; k < 8; ++k) {
                // rotated class assignment: this lane's register k covers
                // j-class k^sig of the batch.
                const int j = jb * 8 + (k ^ (int)sig);
                const float4 ab = shAB[j * 32 + lane];
                const float2 g  = shG[j * 32 + lane];
                const float yA0 = fmaf(ab.x, qA0, fmaf(ab.z, zA0, g.x));
                const float yA1 = fmaf(ab.y, qA1, fmaf(ab.w, zA1, g.y));
                const float yB0 = fmaf(ab.x, qB0, fmaf(ab.z, zB0, g.x));
                const float yB1 = fmaf(ab.y, qB1, fmaf(ab.w, zB1, g.y));
                const __half2 eA = ex2h2(yA0, yA1);
                const __half2 eB = ex2h2(yB0, yB1);
                if (k & 1) {
                    eqA[k >> 1] = __hadd2(eqA[k >> 1], eA);
                    eqB[k >> 1] = __hadd2(eqB[k >> 1], eB);
                } else {
                    eqA[k >> 1] = eA;
                    eqB[k >> 1] = eB;
                }
                tCA[k] = yA0 + yA1;
                tCB[k] = yB0 + yB1;
            }
            // tree-flush half2 exp partials to fp32 accumulators
            {
                const __half2 rA = __hadd2(__hadd2(eqA[0], eqA[1]),
                                           __hadd2(eqA[2], eqA[3]));
                const __half2 rB = __hadd2(__hadd2(eqB[0], eqB[1]),
                                           __hadd2(eqB[2], eqB[3]));
                const float2 fA = __half22float2(rA);
                const float2 fB = __half22float2(rB);
                aA0 += fA.x; aA1 += fA.y;
                aB0 += fB.x; aB1 += fB.y;
            }
            if (jb > 0) {
                lse_up(mA, sA, mred8rot(tPA));
                lse_up(mB, sB, mred8rot(tPB));
            }
            #pragma unroll
            for (int k = 0; k < 8; ++k) { tPA[k] = tCA[k]; tPB[k] = tCB[k]; }
        }
        lse_up(mA, sA, mred8rot(tPA));
        lse_up(mB, sB, mred8rot(tPB));

        // store per-dim chunk partials as half2 scaled by 64 (headroom:
        // max value 64*4.3*64 ~ 17k < 65504; scaling unwound in k2)
        g_psumh[(i0 * NCHUNK + c) * 32 + lane] =
            __floats2half2_rn(aA0 * 64.f, aA1 * 64.f);
        g_psumh[((i0 + 1) * NCHUNK + c) * 32 + lane] =
            __floats2half2_rn(aB0 * 64.f, aB1 * 64.f);
        merge_classes(mA, sA);
        merge_classes(mB, sB);
        if (lane == 0) {
            g_pm[i0 * NCHUNK + c] = mA;
            g_ps[i0 * NCHUNK + c] = sA;
            g_pm[(i0 + 1) * NCHUNK + c] = mB;
            g_ps[(i0 + 1) * NCHUNK + c] = sB;
        }
    }
}

// k2: one warp per i combines the 32 chunk partials; last block also
// computes the final mean (fused former k3).
__global__ __launch_bounds__(256)
void tc_reduce_i(float* __restrict__ out)
{
    __shared__ int  s_last;
    __shared__ float sm[8];

    const int wid  = threadIdx.x >> 5;
    const int lane = threadIdx.x & 31;
    const int i    = blockIdx.x * 8 + wid;

    float s0 = 0.f, s1 = 0.f;
    #pragma unroll
    for (int cc = 0; cc < NCHUNK; ++cc) {
        const float2 v = __half22float2(g_psumh[(i * NCHUNK + cc) * 32 + lane]);
        s0 += v.x; s1 += v.y;
    }
    // each lane's partials carry a x64 scale per dim -> subtract 2*6 in log2
    float t = lg2f(s0) + lg2f(s1) - 12.0f;
    #pragma unroll
    for (int off = 16; off; off >>= 1)
        t += __shfl_xor_sync(0xffffffffu, t, off);

    float ml = g_pm[i * NCHUNK + lane];   // NCHUNK==32: one chunk per lane
    float sl = g_ps[i * NCHUNK + lane];
    #pragma unroll
    for (int off = 16; off; off >>= 1) {
        const float mo = __shfl_xor_sync(0xffffffffu, ml, off);
        const float so = __shfl_xor_sync(0xffffffffu, sl, off);
        const float M  = fmaxf(ml, mo);
        sl = sl * ex2f(ml - M) + so * ex2f(mo - M);
        ml = M;
    }

    if (lane == 0)
        g_val[i] = LN2 * (t - (ml + lg2f(sl)));

    // ---- last-block final mean (fused former k3) ----
    __syncthreads();
    if (threadIdx.x == 0) {
        __threadfence();                       // flush g_val to L2
        s_last = (atomicAdd(&g_count, 1) == K2GRID - 1);
    }
    __syncthreads();
    if (s_last) {
        const int tt = threadIdx.x;
        float v = 0.f;
        #pragma unroll
        for (int k = 0; k < 8; ++k)
            v += __ldcg(&g_val[tt + k * 256]); // bypass L1: other blocks' data
        #pragma unroll
        for (int off = 16; off; off >>= 1)
            v += __shfl_xor_sync(0xffffffffu, v, off);
        if ((tt & 31) == 0) sm[tt >> 5] = v;
        __syncthreads();
        if (tt == 0) {
            float r = 0.f;
            #pragma unroll
            for (int k = 0; k < 8; ++k) r += sm[k];
            out[0] = r * (1.0f / (float)NPTS);
            g_count = 0;                       // reset for next graph replay
        }
    }
}

extern "C" void kernel_launch(void* const* d_in, const int* in_sizes, int n_in,
                              void* d_out, int out_size)
{
    const float* z  = (const float*)d_in[0];
    const float* zm = (const float*)d_in[1];
    const float* zl = (const float*)d_in[2];
    tc_coeff_kernel<<<NPTS * DDIM / 1024, 256>>>(zm, zl);
    tc_main_kernel<<<NBLOCKS, 256>>>(z);
    tc_reduce_i<<<K2GRID, 256>>>((float*)d_out);
}

// round 17
// speedup vs baseline: 1.2776x; 1.0940x over previous
#include <cuda_runtime.h>
#include <cuda_fp16.h>

// TCLoss, N=2048, D=64.
// y_ijd = LOG2E * log N(z_i,d ; m_j,d, exp(lv_j,d)) = a_jd*z^2 + b_jd*z + g_jd
// out = mean_i [ LN2*( sum_d log2 sum_j 2^y  -  log2sumexp2_j sum_d y ) ]
//
// k0: precompute coeffs (AB float4 (a0,a1,b0,b1), G float2 per (j,dim-pair)).
// k1: persistent main. Warp owns 4 i's (crossbar per coefficient load
//     amortized over 4 pairs -> 1.5 cyc/pair, half of the 2-i scheme), lane
//     owns dims {2l,2l+1}; 64-j smem tile, 2 blocks/SM. fp32 FMA; f16x2
//     per-dim exps; rotated SEL-free butterfly + fp32 online LSE (no software
//     pipeline -- 4 independent butterfly chains provide the ILP). psum
//     stored as half2 x64.
// k2: per-i reduction over 32 chunk partials + fused final mean (last-block
//     pattern, self-resetting counter, deterministic fixed-tree sum).

#define LOG2E   1.44269504088896340736f
#define LN2     0.69314718055994530942f
#define LOG2PI  1.83787706640934548356f
#define NEG_INF __int_as_float(0xff800000)

#define NPTS    2048
#define DDIM    64
#define TJ      64                   // j's per chunk
#define NCHUNK  (NPTS / TJ)          // 32
#define IPB     32                   // i's per block (8 warps x 4)
#define NGROUP  (NPTS / IPB)         // 64
#define NUNITS  (NGROUP * NCHUNK)    // 2048
#define NBLOCKS 296                  // 148 SMs x 2 resident blocks
#define K2GRID  (NPTS / 8)           // 256 blocks in the reduce kernel

// Static scratch (no allocation).
__device__ float4  g_cAB[NPTS * DDIM / 2];        // (a0,a1,b0,b1) per (j, dim-pair)
__device__ float2  g_cG[NPTS * DDIM / 2];         // (g0,g1) per (j, dim-pair)
__device__ __half2 g_psumh[NPTS * NCHUNK * 32];   // per-(i,chunk) per-dim-pair sums (x64)
__device__ float   g_pm[NPTS * NCHUNK];           // per-(i,chunk) LSE max (log2)
__device__ float   g_ps[NPTS * NCHUNK];           // per-(i,chunk) LSE scaled sum
__device__ float   g_val[NPTS];                   // per-i result
__device__ int     g_count;                       // last-block counter (zero-init)

static __device__ __forceinline__ float ex2f(float x) {
    float r; asm("ex2.approx.ftz.f32 %0, %1;" : "=f"(r) : "f"(x)); return r;
}
static __device__ __forceinline__ float lg2f(float x) {
    float r; asm("lg2.approx.f32 %0, %1;" : "=f"(r) : "f"(x)); return r;
}
// Pack two fp32 -> half2 (single F2FP.PACK), then 2^x on both halves (1 MUFU).
static __device__ __forceinline__ __half2 ex2h2(float x, float y) {
    __half2 h = __floats2half2_rn(x, y);
    __half2 r;
    asm("ex2.approx.f16x2 %0, %1;"
        : "=r"(*reinterpret_cast<unsigned*>(&r))
        : "r"(*reinterpret_cast<const unsigned*>(&h)));
    return r;
}

// Online base-2 logsumexp update with a single EX2.
static __device__ __forceinline__ void lse_up(float& m, float& s, float S) {
    const float d = S - m;
    const float e = ex2f(-fabsf(d));   // ex2(-inf)=0 handles first call (m=-inf)
    if (d > 0.f) { s = fmaf(s, e, 1.f); m = S; }
    else         { s += e; }
}

// Rotated multi-value warp reduction (SEL-free): lane l's t[k] holds the
// partial for j-class (k ^ sigma), sigma = (l>>2)&7. Returns, on every lane,
// the full 32-lane sum of class (lane>>2)&7.
static __device__ __forceinline__ float mred8rot(float t[8]) {
    #pragma unroll
    for (int k = 0; k < 4; ++k)
        t[k] += __shfl_xor_sync(0xffffffffu, t[k ^ 4], 16);
    #pragma unroll
    for (int k = 0; k < 2; ++k)
        t[k] += __shfl_xor_sync(0xffffffffu, t[k ^ 2], 8);
    t[0] += __shfl_xor_sync(0xffffffffu, t[1], 4);
    float v = t[0];
    v += __shfl_xor_sync(0xffffffffu, v, 2);
    v += __shfl_xor_sync(0xffffffffu, v, 1);
    return v;
}

// Merge per-lane (m,s) across the 8 j-classes (lane bits 2..4).
static __device__ __forceinline__ void merge_classes(float& m, float& s) {
    #pragma unroll
    for (int off = 4; off <= 16; off <<= 1) {
        const float mo = __shfl_xor_sync(0xffffffffu, m, off);
        const float so = __shfl_xor_sync(0xffffffffu, s, off);
        const float M  = fmaxf(m, mo);
        s = s * ex2f(m - M) + so * ex2f(mo - M);
        m = M;
    }
}

static __device__ __forceinline__ void coeffs(float mm, float lv,
                                              float& a, float& b, float& g) {
    const float iv = ex2f(-LOG2E * lv);          // exp(-lv)
    const float w  = -0.5f * LOG2E * iv;
    const float t  = w * mm;
    a = w;
    b = -(t + t);
    g = fmaf(t, mm, -0.5f * LOG2E * (lv + LOG2PI));
}

// k0: precompute packed coefficient arrays.
__global__ __launch_bounds__(256)
void tc_coeff_kernel(const float* __restrict__ zmean, const float* __restrict__ zlv)
{
    const int e = blockIdx.x * 256 + threadIdx.x;   // [0, 32768)
    const int j = e >> 4;
    const int f = e & 15;                           // float4 index within row
    const float4 mv = ((const float4*)zmean)[e];
    const float4 lv = ((const float4*)zlv)[e];
    float a0, b0, g0, a1, b1, g1, a2, b2, g2, a3, b3, g3;
    coeffs(mv.x, lv.x, a0, b0, g0);
    coeffs(mv.y, lv.y, a1, b1, g1);
    coeffs(mv.z, lv.z, a2, b2, g2);
    coeffs(mv.w, lv.w, a3, b3, g3);
    g_cAB[(j << 5) + 2 * f]     = make_float4(a0, a1, b0, b1);
    g_cAB[(j << 5) + 2 * f + 1] = make_float4(a2, a3, b2, b3);
    g_cG[(j << 5) + 2 * f]      = make_float2(g0, g1);
    g_cG[(j << 5) + 2 * f + 1]  = make_float2(g2, g3);
}

// k1: main pairwise kernel (4 i's per warp).
__global__ __launch_bounds__(256, 2)
void tc_main_kernel(const float* __restrict__ z)
{
    __shared__ float4 shAB[TJ * 32];   // 32 KB
    __shared__ float2 shG[TJ * 32];    // 16 KB

    const int tid  = threadIdx.x;
    const int wid  = tid >> 5;
    const unsigned lane = tid & 31;
    const unsigned sig  = (lane >> 2) & 7;   // rotation for SEL-free butterfly

    for (int u = blockIdx.x; u < NUNITS; u += NBLOCKS) {
        const int ig = u & (NGROUP - 1);
        const int c  = u >> 6;
        const int js = c * TJ;

        __syncthreads();  // previous unit's readers done
        {
            const float4* pab = g_cAB + js * 32;
            const float4* pg  = (const float4*)(g_cG + js * 32);
            #pragma unroll
            for (int e = tid; e < TJ * 32; e += 256)
                shAB[e] = pab[e];
            #pragma unroll
            for (int e = tid; e < TJ * 16; e += 256)
                ((float4*)shG)[e] = pg[e];
        }
        __syncthreads();

        const int i0 = ig * IPB + wid * 4;
        float z0[4], z1[4], q0[4], q1[4], ac0[4], ac1[4], mm[4], ss[4];
        #pragma unroll
        for (int ii = 0; ii < 4; ++ii) {
            const float2 zv = ((const float2*)z)[(i0 + ii) * 32 + lane];
            z0[ii] = zv.x; z1[ii] = zv.y;
            q0[ii] = zv.x * zv.x; q1[ii] = zv.y * zv.y;
            ac0[ii] = 0.f; ac1[ii] = 0.f;
            mm[ii] = NEG_INF; ss[ii] = 0.f;
        }

        #pragma unroll 1
        for (int jb = 0; jb < TJ / 8; ++jb) {
            float t[4][8];
            __half2 eq[4][4];          // pairwise half2 exp accumulators
            #pragma unroll
            for (int k = 0; k < 8; ++k) {
                // rotated class assignment: this lane's register k covers
                // j-class k^sig of the batch.
                const int j = jb * 8 + (k ^ (int)sig);
                const float4 ab = shAB[j * 32 + lane];
                const float2 g  = shG[j * 32 + lane];
                #pragma unroll
                for (int ii = 0; ii < 4; ++ii) {
                    const float y0 = fmaf(ab.x, q0[ii], fmaf(ab.z, z0[ii], g.x));
                    const float y1 = fmaf(ab.y, q1[ii], fmaf(ab.w, z1[ii], g.y));
                    const __half2 e = ex2h2(y0, y1);
                    if (k & 1) eq[ii][k >> 1] = __hadd2(eq[ii][k >> 1], e);
                    else       eq[ii][k >> 1] = e;
                    t[ii][k] = y0 + y1;
                }
            }
            // tree-flush half2 exp partials to fp32 accumulators
            #pragma unroll
            for (int ii = 0; ii < 4; ++ii) {
                const __half2 r = __hadd2(__hadd2(eq[ii][0], eq[ii][1]),
                                          __hadd2(eq[ii][2], eq[ii][3]));
                const float2 f = __half22float2(r);
                ac0[ii] += f.x;
                ac1[ii] += f.y;
            }
            // 4 independent rotated butterflies (ILP hides shuffle latency)
            #pragma unroll
            for (int ii = 0; ii < 4; ++ii)
                lse_up(mm[ii], ss[ii], mred8rot(t[ii]));
        }

        #pragma unroll
        for (int ii = 0; ii < 4; ++ii) {
            // store per-dim chunk partials as half2 scaled by 64 (headroom:
            // max value 64*4.3*64 ~ 17k < 65504; scaling unwound in k2)
            g_psumh[((i0 + ii) * NCHUNK + c) * 32 + lane] =
                __floats2half2_rn(ac0[ii] * 64.f, ac1[ii] * 64.f);
            merge_classes(mm[ii], ss[ii]);
            if (lane == 0) {
                g_pm[(i0 + ii) * NCHUNK + c] = mm[ii];
                g_ps[(i0 + ii) * NCHUNK + c] = ss[ii];
            }
        }
    }
}

// k2: one warp per i combines the 32 chunk partials; last block also
// computes the final mean (fused former k3).
__global__ __launch_bounds__(256)
void tc_reduce_i(float* __restrict__ out)
{
    __shared__ int  s_last;
    __shared__ float sm[8];

    const int wid  = threadIdx.x >> 5;
    const int lane = threadIdx.x & 31;
    const int i    = blockIdx.x * 8 + wid;

    float s0 = 0.f, s1 = 0.f;
    #pragma unroll
    for (int cc = 0; cc < NCHUNK; ++cc) {
        const float2 v = __half22float2(g_psumh[(i * NCHUNK + cc) * 32 + lane]);
        s0 += v.x; s1 += v.y;
    }
    // each lane's partials carry a x64 scale per dim -> subtract 2*6 in log2
    float t = lg2f(s0) + lg2f(s1) - 12.0f;
    #pragma unroll
    for (int off = 16; off; off >>= 1)
        t += __shfl_xor_sync(0xffffffffu, t, off);

    float ml = g_pm[i * NCHUNK + lane];   // NCHUNK==32: one chunk per lane
    float sl = g_ps[i * NCHUNK + lane];
    #pragma unroll
    for (int off = 16; off; off >>= 1) {
        const float mo = __shfl_xor_sync(0xffffffffu, ml, off);
        const float so = __shfl_xor_sync(0xffffffffu, sl, off);
        const float M  = fmaxf(ml, mo);
        sl = sl * ex2f(ml - M) + so * ex2f(mo - M);
        ml = M;
    }

    if (lane == 0)
        g_val[i] = LN2 * (t - (ml + lg2f(sl)));

    // ---- last-block final mean (fused former k3) ----
    __syncthreads();
    if (threadIdx.x == 0) {
        __threadfence();                       // flush g_val to L2
        s_last = (atomicAdd(&g_count, 1) == K2GRID - 1);
    }
    __syncthreads();
    if (s_last) {
        const int tt = threadIdx.x;
        float v = 0.f;
        #pragma unroll
        for (int k = 0; k < 8; ++k)
            v += __ldcg(&g_val[tt + k * 256]); // bypass L1: other blocks' data
        #pragma unroll
        for (int off = 16; off; off >>= 1)
            v += __shfl_xor_sync(0xffffffffu, v, off);
        if ((tt & 31) == 0) sm[tt >> 5] = v;
        __syncthreads();
        if (tt == 0) {
            float r = 0.f;
            #pragma unroll
            for (int k = 0; k < 8; ++k) r += sm[k];
            out[0] = r * (1.0f / (float)NPTS);
            g_count = 0;                       // reset for next graph replay
        }
    }
}

extern "C" void kernel_launch(void* const* d_in, const int* in_sizes, int n_in,
                              void* d_out, int out_size)
{
    const float* z  = (const float*)d_in[0];
    const float* zm = (const float*)d_in[1];
    const float* zl = (const float*)d_in[2];
    tc_coeff_kernel<<<NPTS * DDIM / 1024, 256>>>(zm, zl);
    tc_main_kernel<<<NBLOCKS, 256>>>(z);
    tc_reduce_i<<<K2GRID, 256>>>((float*)d_out);
}